// round 1
// baseline (speedup 1.0000x reference)
#include <cuda_runtime.h>
#include <cstdint>

#define BB   32
#define NN   1024
#define ND   14
#define HID  64
#define HEADD 128
#define MAXN 64
#define ROWS (BB*NN)   // 32768

// ---------------- scratch (device globals; no allocations) ----------------
__device__ int   g_nbr[ROWS * MAXN];   // per-row neighbor column indices (within batch)
__device__ int   g_cnt[ROWS];          // per-row neighbor count (= degree, values are 0/1)
__device__ float g_dinv[ROWS];         // rsqrt(max(deg,1))
__device__ float g_bufA[ROWS * HID];
__device__ float g_bufB[ROWS * HID];

// ---------------------------------------------------------------------------
// K1: one warp per adjacency row. Read 1024 floats (float4), extract nonzero
// column indices via ballot-free per-lane scan, store ELL list + dinv.
// Adjacency is read exactly once (128 MB) -> HBM-bound.
// ---------------------------------------------------------------------------
__global__ void k_adj(const float4* __restrict__ adj4) {
    int gtid = blockIdx.x * blockDim.x + threadIdx.x;
    int row  = gtid >> 5;
    int lane = gtid & 31;
    if (row >= ROWS) return;

    const float4* rp = adj4 + (size_t)row * (NN / 4);
    int base = row * MAXN;
    int cnt = 0;

    #pragma unroll
    for (int k = 0; k < NN / 128; ++k) {         // 8 iterations
        float4 v = rp[k * 32 + lane];
        int col0 = (k * 32 + lane) * 4;
        int m = (v.x != 0.f ? 1 : 0) | (v.y != 0.f ? 2 : 0)
              | (v.z != 0.f ? 4 : 0) | (v.w != 0.f ? 8 : 0);
        int c = __popc(m);
        // inclusive warp scan of c
        int x = c;
        #pragma unroll
        for (int d = 1; d < 32; d <<= 1) {
            int y = __shfl_up_sync(0xffffffffu, x, d);
            if (lane >= d) x += y;
        }
        int off = cnt + x - c;                   // exclusive offset for this lane
        int tot = __shfl_sync(0xffffffffu, x, 31);
        int w = off;
        if (m & 1) { if (w < MAXN) g_nbr[base + w] = col0;     w++; }
        if (m & 2) { if (w < MAXN) g_nbr[base + w] = col0 + 1; w++; }
        if (m & 4) { if (w < MAXN) g_nbr[base + w] = col0 + 2; w++; }
        if (m & 8) { if (w < MAXN) g_nbr[base + w] = col0 + 3; w++; }
        cnt += tot;
    }
    if (lane == 0) {
        g_cnt[row]  = cnt;
        g_dinv[row] = rsqrtf((float)(cnt > 0 ? cnt : 1));
    }
}

// ---------------------------------------------------------------------------
// K2: z0[row] = dinv[row] * (x[row] @ W1)      (pre-scaled first-layer features)
// 64 threads per row (one output channel each), 4 rows per 256-thread block.
// ---------------------------------------------------------------------------
__global__ void k_lin0(const float* __restrict__ x, const float* __restrict__ W1,
                       float* __restrict__ out) {
    int g   = threadIdx.x >> 6;                  // row group 0..3
    int t   = threadIdx.x & 63;                  // output channel
    int row = blockIdx.x * 4 + g;

    __shared__ float sx[4][16];
    if (t < ND) sx[g][t] = x[(size_t)row * ND + t];
    __syncthreads();

    float a = 0.f;
    #pragma unroll
    for (int c = 0; c < ND; ++c) a += sx[g][c] * W1[c * HID + t];
    out[(size_t)row * HID + t] = a * g_dinv[row];
}

// ---------------------------------------------------------------------------
// K3: fused aggregation layer.
//   s      = sum_{j in nbr(i)} zin[j]            (zin rows are pre-scaled by dinv_j)
//   h      = relu(dinv_i * s + bias)
//   HAS_MV:  out = dinv_i * (h @ Wnext)          (pre-scaled input for next layer)
//   !HAS_MV: out = h                              (final hidden, used for pooling)
// 64 threads per row, 4 rows per block.
// ---------------------------------------------------------------------------
template <int HAS_MV>
__global__ void k_agg(const float* __restrict__ zin, const float* __restrict__ bias,
                      const float* __restrict__ Wnext, float* __restrict__ out) {
    int g   = threadIdx.x >> 6;
    int t   = threadIdx.x & 63;
    int row = blockIdx.x * 4 + g;

    int cnt  = g_cnt[row]; if (cnt > MAXN) cnt = MAXN;
    int base = row * MAXN;
    int bbase = (row >> 10) << 10;               // batch * N
    float dinv_i = g_dinv[row];

    __shared__ int   sidx[4][MAXN];
    __shared__ float sh[4][HID];
    if (t < cnt) sidx[g][t] = g_nbr[base + t];
    __syncthreads();

    float acc = 0.f;
    for (int k = 0; k < cnt; ++k) {
        int col = sidx[g][k];
        acc += zin[(size_t)(bbase + col) * HID + t];
    }
    float h = fmaxf(dinv_i * acc + bias[t], 0.f);

    if (!HAS_MV) {
        out[(size_t)row * HID + t] = h;
        return;
    }
    sh[g][t] = h;
    __syncthreads();
    float a2 = 0.f;
    const float* shr = sh[g];
    #pragma unroll
    for (int c = 0; c < HID; ++c) a2 += shr[c] * Wnext[c * HID + t];
    out[(size_t)row * HID + t] = dinv_i * a2;
}

// ---------------------------------------------------------------------------
// K4: per batch: pooled = mean_N(h3); head = relu(pooled@Wf1+bf1); out = head@Wf2+bf2
// One 256-thread block per batch element.
// ---------------------------------------------------------------------------
__global__ void k_final(const float* __restrict__ h3,
                        const float* __restrict__ Wf1, const float* __restrict__ bf1,
                        const float* __restrict__ Wf2, const float* __restrict__ bf2,
                        float* __restrict__ out) {
    int b   = blockIdx.x;
    int tid = threadIdx.x;
    int t   = tid & 63;
    int rg  = tid >> 6;                          // 4 row groups

    __shared__ float part[256];
    __shared__ float pooled[HID];
    __shared__ float hred[HEADD];

    float acc = 0.f;
    const float* hb = h3 + (size_t)b * NN * HID;
    for (int i = rg; i < NN; i += 4)
        acc += hb[(size_t)i * HID + t];
    part[tid] = acc;
    __syncthreads();
    if (tid < HID)
        pooled[t] = (part[t] + part[t + 64] + part[t + 128] + part[t + 192]) * (1.f / NN);
    __syncthreads();

    if (tid < HEADD) {
        float a = bf1[tid];
        #pragma unroll
        for (int c = 0; c < HID; ++c) a += pooled[c] * Wf1[c * HEADD + tid];
        a = fmaxf(a, 0.f);
        hred[tid] = a * Wf2[tid];
    }
    __syncthreads();
    if (tid < 32) {
        float s = hred[tid] + hred[tid + 32] + hred[tid + 64] + hred[tid + 96];
        #pragma unroll
        for (int d = 16; d; d >>= 1) s += __shfl_down_sync(0xffffffffu, s, d);
        if (tid == 0) out[b] = s + bf2[0];
    }
}

// ---------------------------------------------------------------------------
extern "C" void kernel_launch(void* const* d_in, const int* in_sizes, int n_in,
                              void* d_out, int out_size) {
    const float* x    = (const float*)d_in[0];
    const float* adj  = (const float*)d_in[1];
    const float* W1   = (const float*)d_in[2];
    const float* b1   = (const float*)d_in[3];
    const float* W2   = (const float*)d_in[4];
    const float* b2   = (const float*)d_in[5];
    const float* W3   = (const float*)d_in[6];
    const float* b3   = (const float*)d_in[7];
    const float* Wf1  = (const float*)d_in[8];
    const float* bf1  = (const float*)d_in[9];
    const float* Wf2  = (const float*)d_in[10];
    const float* bf2  = (const float*)d_in[11];
    float* out = (float*)d_out;

    float *bufA, *bufB;
    cudaGetSymbolAddress((void**)&bufA, g_bufA);
    cudaGetSymbolAddress((void**)&bufB, g_bufB);

    // 1. adjacency -> ELL neighbor lists + dinv (one 128MB pass)
    k_adj<<<ROWS * 32 / 256, 256>>>((const float4*)adj);
    // 2. z0 = dinv * (x @ W1)
    k_lin0<<<ROWS / 4, 256>>>(x, W1, bufA);
    // 3. layer1 agg + matvec with W2  -> z1
    k_agg<1><<<ROWS / 4, 256>>>(bufA, b1, W2, bufB);
    // 4. layer2 agg + matvec with W3  -> z2
    k_agg<1><<<ROWS / 4, 256>>>(bufB, b2, W3, bufA);
    // 5. layer3 agg -> h3
    k_agg<0><<<ROWS / 4, 256>>>(bufA, b3, nullptr, bufB);
    // 6. pool + MLP head
    k_final<<<BB, 256>>>(bufB, Wf1, bf1, Wf2, bf2, out);
}